// round 1
// baseline (speedup 1.0000x reference)
#include <cuda_runtime.h>
#include <math.h>

#define NJ 24
#define NV 20000
#define NG 2
#define HID 128
#define TILE_V 128
#define NTHR 256
#define KCH 32
#define EPSV 1e-8f

// Scratch (allowed: __device__ globals, no allocation)
__device__ float g_c[NJ][4];
__device__ float g_geom[NJ][NG][16];   // [0:3]=tr_o [3:6]=u [6]=cbias [7:10]=Jpose [10:13]=Jtr_center
__device__ float g_pred[NJ][NV];

__device__ __forceinline__ float sp100(float x) {
    // softplus(100*x)/100, numerically stable, matches jax.nn.softplus in fp32
    float t = 100.0f * x;
    if (t > 20.0f) return x;
    return log1pf(expf(t)) * 0.01f;
}

__device__ __forceinline__ float ra_elu(float x) {
    // elu(x-1)+1
    return (x - 1.0f) > 0.0f ? x : expf(x - 1.0f);
}

// ---------------------------------------------------------------------------
// Per-part precompute: cond MLP (288->16->16->4) + blending-weight constants
// ---------------------------------------------------------------------------
__global__ void pre_kernel(const float* __restrict__ Bcond,
                           const float* __restrict__ Bneigh,
                           const float* __restrict__ alpha,
                           const float* __restrict__ beta,
                           const float* __restrict__ cW0, const float* __restrict__ cb0,
                           const float* __restrict__ cW1, const float* __restrict__ cb1,
                           const float* __restrict__ cW2, const float* __restrict__ cb2)
{
    int j = blockIdx.x;
    int lane = threadIdx.x;
    __shared__ float c0[16], c1[16];

    if (lane < 16) {
        float s = cb0[j * 16 + lane];
        const float* w = cW0 + (size_t)j * 288 * 16 + lane;
        const float* cond = Bcond + j * 288;
        for (int k = 0; k < 288; k++) s += cond[k] * w[k * 16];
        c0[lane] = sp100(s);
    }
    __syncthreads();
    if (lane < 16) {
        float s = cb1[j * 16 + lane];
        const float* w = cW1 + j * 16 * 16 + lane;
        for (int k = 0; k < 16; k++) s += c0[k] * w[k * 16];
        c1[lane] = sp100(s);
    }
    __syncthreads();
    if (lane < 4) {
        float s = cb2[j * 4 + lane];
        const float* w = cW2 + j * 16 * 4 + lane;
        for (int k = 0; k < 16; k++) s += c1[k] * w[k * 4];
        g_c[j][lane] = s;
    }

    if (lane < NG) {
        int gi = lane;
        const float* bn = Bneigh + ((j * NG + gi) * 5) * 3;
        float Jt[3] = { bn[0], bn[1], bn[2] };    // Jtr_this  (self)
        float Jc[3] = { bn[3], bn[4], bn[5] };    // Jtr_center
        float Jo[3] = { bn[6], bn[7], bn[8] };    // Jtr_other (neigh)
        float Jp[3] = { bn[9], bn[10], bn[11] };  // Jpose
        int bt = (int)bn[12];
        int bo = (int)bn[13];

        float a_n  = ra_elu(alpha[bo * NJ + bt]);
        float a_s  = ra_elu(alpha[bt * NJ + bo]);
        float be_n = beta[bo * NJ + bt];
        float be_s = beta[bt * NJ + bo];

        float nb_n = 0.f, nb_s = 0.f;
        for (int d = 0; d < 3; d++) {
            float tn = Jo[d] - Jc[d]; nb_n += tn * tn;
            float ts = Jt[d] - Jc[d]; nb_s += ts * ts;
        }
        nb_n = sqrtf(nb_n); nb_s = sqrtf(nb_s);

        float vn[3], vs[3];
        float f1 = nb_n / (nb_n + nb_s + EPSV);
        for (int d = 0; d < 3; d++) vn[d] = (Jo[d] - Jt[d]) * f1;
        float f2 = nb_s / (nb_n + EPSV);
        for (int d = 0; d < 3; d++) vs[d] = -vn[d] * f2;

        float n_n = 0.f, n_s = 0.f;
        for (int d = 0; d < 3; d++) { n_n += vn[d] * vn[d]; n_s += vs[d] * vs[d]; }
        n_n = sqrtf(n_n); n_s = sqrtf(n_s);

        float cn = a_n / ((n_n + EPSV) * (n_n + EPSV));
        float cs = a_s / ((n_s + EPSV) * (n_s + EPSV));

        float* gg = g_geom[j][gi];
        for (int d = 0; d < 3; d++) gg[d]     = Jo[d] - vn[d];              // tr_o
        for (int d = 0; d < 3; d++) gg[3 + d] = vn[d] * cn - vs[d] * cs;    // u
        gg[6] = be_n - be_s;                                                // cbias
        for (int d = 0; d < 3; d++) gg[7 + d]  = Jp[d];
        for (int d = 0; d < 3; d++) gg[10 + d] = Jc[d];
    }
}

// ---------------------------------------------------------------------------
// Main kernel: one (part j, 128-point tile) per block.
// Geometry -> x[7] -> 7x128 -> 128x128 -> 128x128 -> 128x1 grouped MLP.
// 256 threads, per-thread 8x8 register micro-tile for the hidden GEMMs.
// ---------------------------------------------------------------------------
__global__ __launch_bounds__(NTHR, 2) void main_kernel(
    const float* __restrict__ pts, const float* __restrict__ Btr, const float* __restrict__ Brot,
    const float* __restrict__ W0, const float* __restrict__ b0,
    const float* __restrict__ W1, const float* __restrict__ b1,
    const float* __restrict__ W2, const float* __restrict__ b2,
    const float* __restrict__ W3, const float* __restrict__ b3)
{
    extern __shared__ float smem[];
    float* xs   = smem;                   // TILE_V * 8
    float* h    = xs + TILE_V * 8;        // TILE_V * 132 (padded rows)
    float* Ws   = h + TILE_V * 132;       // KCH * HID (also reused for W0, W3)
    float* bias = Ws + KCH * HID;         // HID

    int tid = threadIdx.x;
    int j   = blockIdx.y;
    int v0  = blockIdx.x * TILE_V;

    // ---- per-point geometry -> xs ----
    if (tid < TILE_V) {
        int v  = v0 + tid;
        int vc = v < NV ? v : NV - 1;
        float px = pts[vc * 3 + 0] - Btr[j * 3 + 0];
        float py = pts[vc * 3 + 1] - Btr[j * 3 + 1];
        float pz = pts[vc * 3 + 2] - Btr[j * 3 + 2];
        const float* R = Brot + j * 9;
        // pts_local = Brot^T @ p
        float plx = R[0] * px + R[3] * py + R[6] * pz;
        float ply = R[1] * px + R[4] * py + R[7] * pz;
        float plz = R[2] * px + R[5] * py + R[8] * pz;

        float ox = 0.f, oy = 0.f, oz = 0.f;
        #pragma unroll
        for (int gi = 0; gi < NG; gi++) {
            const float* gg = g_geom[j][gi];
            float dx = plx - gg[0], dy = ply - gg[1], dz = plz - gg[2];
            float arg = dx * gg[3] + dy * gg[4] + dz * gg[5] + gg[6];
            float w = 1.0f / (1.0f + expf(-arg));
            // axis-angle = -Jpose * w
            float ax = -gg[7] * w, ay = -gg[8] * w, az = -gg[9] * w;
            float ang = sqrtf(ax * ax + ay * ay + az * az);
            float inv = (ang < 1e-12f) ? 1.0f : (1.0f / ang);
            float ux = ax * inv, uy = ay * inv, uz = az * inv;
            float cc = cosf(ang), ss = sinf(ang);
            float C = 1.0f - cc;
            float qx = plx - gg[10], qy = ply - gg[11], qz = plz - gg[12];
            float rx = (cc + ux * ux * C) * qx + (ux * uy * C - uz * ss) * qy + (ux * uz * C + uy * ss) * qz;
            float ry = (uy * ux * C + uz * ss) * qx + (cc + uy * uy * C) * qy + (uy * uz * C - ux * ss) * qz;
            float rz = (uz * ux * C - uy * ss) * qx + (uz * uy * C + ux * ss) * qy + (cc + uz * uz * C) * qz;
            ox += rx + gg[10] - plx;
            oy += ry + gg[11] - ply;
            oz += rz + gg[12] - plz;
        }
        xs[tid * 8 + 0] = plx + ox;
        xs[tid * 8 + 1] = ply + oy;
        xs[tid * 8 + 2] = plz + oz;
        xs[tid * 8 + 3] = g_c[j][0];
        xs[tid * 8 + 4] = g_c[j][1];
        xs[tid * 8 + 5] = g_c[j][2];
        xs[tid * 8 + 6] = g_c[j][3];
        xs[tid * 8 + 7] = 0.f;
    }
    // stage W0 (7x128) and b0
    for (int i = tid; i < 7 * HID; i += NTHR) Ws[i] = W0[j * 7 * HID + i];
    if (tid < HID) bias[tid] = b0[j * HID + tid];
    __syncthreads();

    // ---- layer0: 7 -> 128 ----
    {
        int o = tid & (HID - 1);
        for (int pt = tid >> 7; pt < TILE_V; pt += 2) {
            float acc = bias[o];
            #pragma unroll
            for (int k = 0; k < 7; k++) acc += xs[pt * 8 + k] * Ws[k * HID + o];
            h[pt * 132 + o] = sp100(acc);
        }
    }
    __syncthreads();

    // ---- layers 1,2: 128 -> 128 (register-tiled GEMM) ----
    int tr = tid >> 4;   // point group 0..15
    int tc = tid & 15;   // output group 0..15
    #pragma unroll 1
    for (int layer = 0; layer < 2; layer++) {
        const float* W  = (layer == 0 ? W1 : W2) + (size_t)j * HID * HID;
        const float* bb = (layer == 0 ? b1 : b2) + j * HID;
        if (tid < HID) bias[tid] = bb[tid];

        float acc[8][8];
        #pragma unroll
        for (int pi = 0; pi < 8; pi++)
            #pragma unroll
            for (int oi = 0; oi < 8; oi++) acc[pi][oi] = 0.f;

        for (int kc = 0; kc < HID; kc += KCH) {
            __syncthreads();
            const float4* src = (const float4*)(W + kc * HID);
            float4* dst = (float4*)Ws;
            #pragma unroll
            for (int i = 0; i < (KCH * HID / 4) / NTHR; i++)
                dst[tid + i * NTHR] = src[tid + i * NTHR];
            __syncthreads();
            #pragma unroll 4
            for (int kk = 0; kk < KCH; kk++) {
                float a[8], w[8];
                #pragma unroll
                for (int pi = 0; pi < 8; pi++) a[pi] = h[(tr + 16 * pi) * 132 + kc + kk];
                #pragma unroll
                for (int oi = 0; oi < 8; oi++) w[oi] = Ws[kk * HID + tc + 16 * oi];
                #pragma unroll
                for (int pi = 0; pi < 8; pi++)
                    #pragma unroll
                    for (int oi = 0; oi < 8; oi++)
                        acc[pi][oi] += a[pi] * w[oi];
            }
        }
        __syncthreads();
        #pragma unroll
        for (int pi = 0; pi < 8; pi++) {
            int pt = tr + 16 * pi;
            #pragma unroll
            for (int oi = 0; oi < 8; oi++) {
                int o = tc + 16 * oi;
                h[pt * 132 + o] = sp100(acc[pi][oi] + bias[o]);
            }
        }
        __syncthreads();
    }

    // ---- layer3: 128 -> 1 ----
    if (tid < HID) Ws[tid] = W3[j * HID + tid];
    __syncthreads();
    if (tid < TILE_V) {
        float acc = b3[j];
        #pragma unroll 8
        for (int k = 0; k < HID; k++) acc += h[tid * 132 + k] * Ws[k];
        int v = v0 + tid;
        if (v < NV) g_pred[j][v] = acc;
    }
}

// ---------------------------------------------------------------------------
// Softmin blend over parts
// ---------------------------------------------------------------------------
__global__ void softmin_kernel(float* __restrict__ out) {
    int v = blockIdx.x * blockDim.x + threadIdx.x;
    if (v >= NV) return;
    float p[NJ];
    float m = 3.0e38f;
    #pragma unroll
    for (int j = 0; j < NJ; j++) { p[j] = g_pred[j][v]; m = fminf(m, p[j]); }
    float se = 0.f, sd = 0.f;
    #pragma unroll
    for (int j = 0; j < NJ; j++) {
        float d = p[j] - m;
        float e = expf(-200.0f * d);
        se += e;
        sd += d * e;
    }
    out[v] = sd / se + m;
}

extern "C" void kernel_launch(void* const* d_in, const int* in_sizes, int n_in,
                              void* d_out, int out_size)
{
    const float* pts    = (const float*)d_in[0];
    const float* Bcond  = (const float*)d_in[1];
    const float* Btr    = (const float*)d_in[2];
    const float* Brot   = (const float*)d_in[3];
    const float* Bneigh = (const float*)d_in[4];
    const float* alpha  = (const float*)d_in[5];
    const float* beta   = (const float*)d_in[6];
    const float* cW0 = (const float*)d_in[7];
    const float* cb0 = (const float*)d_in[8];
    const float* cW1 = (const float*)d_in[9];
    const float* cb1 = (const float*)d_in[10];
    const float* cW2 = (const float*)d_in[11];
    const float* cb2 = (const float*)d_in[12];
    const float* W0  = (const float*)d_in[13];
    const float* b0  = (const float*)d_in[14];
    const float* W1  = (const float*)d_in[15];
    const float* b1  = (const float*)d_in[16];
    const float* W2  = (const float*)d_in[17];
    const float* b2  = (const float*)d_in[18];
    const float* W3  = (const float*)d_in[19];
    const float* b3  = (const float*)d_in[20];

    size_t smem_bytes = (size_t)(TILE_V * 8 + TILE_V * 132 + KCH * HID + HID + 32) * sizeof(float);
    cudaFuncSetAttribute(main_kernel, cudaFuncAttributeMaxDynamicSharedMemorySize, (int)smem_bytes);

    pre_kernel<<<NJ, 32>>>(Bcond, Bneigh, alpha, beta, cW0, cb0, cW1, cb1, cW2, cb2);

    dim3 grid((NV + TILE_V - 1) / TILE_V, NJ);
    main_kernel<<<grid, NTHR, smem_bytes>>>(pts, Btr, Brot, W0, b0, W1, b1, W2, b2, W3, b3);

    softmin_kernel<<<(NV + 255) / 256, 256>>>((float*)d_out);
}

// round 5
// speedup vs baseline: 1.9447x; 1.9447x over previous
#include <cuda_runtime.h>
#include <cuda_bf16.h>
#include <math.h>
#include <stdint.h>

#define NJ 24
#define NV 20000
#define NG 2
#define HID 128
#define EPSV 1e-8f
#define TPB 256
#define MTILE 128
#define WSTRIDE 136   // padded row stride (elements) for conflict-free LDS

// smem layout (bytes)
#define OFF_ACT_HI 0
#define OFF_ACT_LO 34816
#define OFF_W_HI   69632
#define OFF_W_LO   104448
#define OFF_F32    139264   // w0s[896], b0s[128], b1s[128], b2s[128], w3s[128]
#define SMEM_BYTES (139264 + (896 + 4 * 128) * 4)

__device__ float g_c[NJ][4];
__device__ float g_geom[NJ][NG][16];
__device__ float g_pred[NJ][NV];
// [layer][hi/lo][j] transposed weights Wt[n][k], stride 136, bf16
__device__ __nv_bfloat16 g_Wt[2][2][NJ][HID * WSTRIDE];

__device__ __forceinline__ float sp100(float x) {
    float t = 100.0f * x;
    if (t > 20.0f) return x;
    return log1pf(expf(t)) * 0.01f;
}
__device__ __forceinline__ float sp100f(float x) {
    return fmaxf(x, 0.0f) + __logf(1.0f + __expf(-fabsf(100.0f * x))) * 0.01f;
}
__device__ __forceinline__ float ra_elu(float x) {
    return (x - 1.0f) > 0.0f ? x : expf(x - 1.0f);
}
__device__ __forceinline__ uint32_t packsplit_hi(float a, float b, uint32_t& lo) {
    __nv_bfloat16 ha = __float2bfloat16_rn(a);
    __nv_bfloat16 hb = __float2bfloat16_rn(b);
    __nv_bfloat16 la = __float2bfloat16_rn(a - __bfloat162float(ha));
    __nv_bfloat16 lb = __float2bfloat16_rn(b - __bfloat162float(hb));
    lo = (uint32_t)__bfloat16_as_ushort(la) | ((uint32_t)__bfloat16_as_ushort(lb) << 16);
    return (uint32_t)__bfloat16_as_ushort(ha) | ((uint32_t)__bfloat16_as_ushort(hb) << 16);
}

__device__ __forceinline__ void mma16816(float* c, const uint32_t* a, const uint32_t* b) {
    asm volatile(
        "mma.sync.aligned.m16n8k16.row.col.f32.bf16.bf16.f32 "
        "{%0,%1,%2,%3}, {%4,%5,%6,%7}, {%8,%9}, {%0,%1,%2,%3};"
        : "+f"(c[0]), "+f"(c[1]), "+f"(c[2]), "+f"(c[3])
        : "r"(a[0]), "r"(a[1]), "r"(a[2]), "r"(a[3]), "r"(b[0]), "r"(b[1]));
}
__device__ __forceinline__ uint32_t lds32(const __nv_bfloat16* p) {
    return *(const uint32_t*)p;
}

// ---------------------------------------------------------------------------
// Per-part precompute (cond MLP + blending constants)
// ---------------------------------------------------------------------------
__global__ void pre_kernel(const float* __restrict__ Bcond, const float* __restrict__ Bneigh,
                           const float* __restrict__ alpha, const float* __restrict__ beta,
                           const float* __restrict__ cW0, const float* __restrict__ cb0,
                           const float* __restrict__ cW1, const float* __restrict__ cb1,
                           const float* __restrict__ cW2, const float* __restrict__ cb2)
{
    int j = blockIdx.x, lane = threadIdx.x;
    __shared__ float c0[16], c1[16];
    if (lane < 16) {
        float s = cb0[j * 16 + lane];
        const float* w = cW0 + (size_t)j * 288 * 16 + lane;
        const float* cond = Bcond + j * 288;
        for (int k = 0; k < 288; k++) s += cond[k] * w[k * 16];
        c0[lane] = sp100(s);
    }
    __syncthreads();
    if (lane < 16) {
        float s = cb1[j * 16 + lane];
        const float* w = cW1 + j * 256 + lane;
        for (int k = 0; k < 16; k++) s += c0[k] * w[k * 16];
        c1[lane] = sp100(s);
    }
    __syncthreads();
    if (lane < 4) {
        float s = cb2[j * 4 + lane];
        const float* w = cW2 + j * 64 + lane;
        for (int k = 0; k < 16; k++) s += c1[k] * w[k * 4];
        g_c[j][lane] = s;
    }
    if (lane < NG) {
        int gi = lane;
        const float* bn = Bneigh + ((j * NG + gi) * 5) * 3;
        float Jt[3] = { bn[0], bn[1], bn[2] };
        float Jc[3] = { bn[3], bn[4], bn[5] };
        float Jo[3] = { bn[6], bn[7], bn[8] };
        float Jp[3] = { bn[9], bn[10], bn[11] };
        int bt = (int)bn[12], bo = (int)bn[13];
        float a_n = ra_elu(alpha[bo * NJ + bt]);
        float a_s = ra_elu(alpha[bt * NJ + bo]);
        float be_n = beta[bo * NJ + bt];
        float be_s = beta[bt * NJ + bo];
        float nb_n = 0.f, nb_s = 0.f;
        for (int d = 0; d < 3; d++) {
            float tn = Jo[d] - Jc[d]; nb_n += tn * tn;
            float ts = Jt[d] - Jc[d]; nb_s += ts * ts;
        }
        nb_n = sqrtf(nb_n); nb_s = sqrtf(nb_s);
        float vn[3], vs[3];
        float f1 = nb_n / (nb_n + nb_s + EPSV);
        for (int d = 0; d < 3; d++) vn[d] = (Jo[d] - Jt[d]) * f1;
        float f2 = nb_s / (nb_n + EPSV);
        for (int d = 0; d < 3; d++) vs[d] = -vn[d] * f2;
        float n_n = 0.f, n_s = 0.f;
        for (int d = 0; d < 3; d++) { n_n += vn[d] * vn[d]; n_s += vs[d] * vs[d]; }
        n_n = sqrtf(n_n); n_s = sqrtf(n_s);
        float cn = a_n / ((n_n + EPSV) * (n_n + EPSV));
        float cs = a_s / ((n_s + EPSV) * (n_s + EPSV));
        float* gg = g_geom[j][gi];
        for (int d = 0; d < 3; d++) gg[d] = Jo[d] - vn[d];
        for (int d = 0; d < 3; d++) gg[3 + d] = vn[d] * cn - vs[d] * cs;
        gg[6] = be_n - be_s;
        for (int d = 0; d < 3; d++) gg[7 + d] = Jp[d];
        for (int d = 0; d < 3; d++) gg[10 + d] = Jc[d];
    }
}

// ---------------------------------------------------------------------------
// Weight conversion: fp32 W[k][n] -> bf16 hi/lo transposed Wt[n][k], stride 136
// ---------------------------------------------------------------------------
__global__ void wconv_kernel(const float* __restrict__ W1, const float* __restrict__ W2) {
    int j = blockIdx.x, layer = blockIdx.y;
    const float* W = (layer == 0 ? W1 : W2) + (size_t)j * HID * HID;
    __nv_bfloat16* dh = &g_Wt[layer][0][j][0];
    __nv_bfloat16* dl = &g_Wt[layer][1][j][0];
    for (int idx = threadIdx.x; idx < HID * WSTRIDE; idx += blockDim.x) {
        int n = idx / WSTRIDE, k = idx - n * WSTRIDE;
        if (k < HID) {
            float w = W[k * HID + n];
            __nv_bfloat16 h = __float2bfloat16_rn(w);
            __nv_bfloat16 l = __float2bfloat16_rn(w - __bfloat162float(h));
            dh[idx] = h; dl[idx] = l;
        } else {
            dh[idx] = __float2bfloat16_rn(0.f);
            dl[idx] = __float2bfloat16_rn(0.f);
        }
    }
}

// ---------------------------------------------------------------------------
// Main kernel: 128 points x 1 part per CTA, mma.sync bf16 3-pass hidden layers
// ---------------------------------------------------------------------------
__global__ __launch_bounds__(TPB, 1) void main_kernel(
    const float* __restrict__ pts, const float* __restrict__ Btr, const float* __restrict__ Brot,
    const float* __restrict__ W0, const float* __restrict__ b0,
    const float* __restrict__ b1, const float* __restrict__ b2,
    const float* __restrict__ W3, const float* __restrict__ b3)
{
    extern __shared__ char sm[];
    __nv_bfloat16* actHi = (__nv_bfloat16*)(sm + OFF_ACT_HI);
    __nv_bfloat16* actLo = (__nv_bfloat16*)(sm + OFF_ACT_LO);
    __nv_bfloat16* wHi   = (__nv_bfloat16*)(sm + OFF_W_HI);
    __nv_bfloat16* wLo   = (__nv_bfloat16*)(sm + OFF_W_LO);
    float* w0s = (float*)(sm + OFF_F32);
    float* b0s = w0s + 896;
    float* b1s = b0s + 128;
    float* b2s = b1s + 128;
    float* w3s = b2s + 128;

    int tid = threadIdx.x;
    int j = blockIdx.y;
    int v0 = blockIdx.x * MTILE;
    int w = tid >> 5, lane = tid & 31;
    int g = lane >> 2, tig = lane & 3;

    // ---- stage layer-1 weights + w0 + biases ----
    {
        const uint4* s1 = (const uint4*)&g_Wt[0][0][j][0];
        const uint4* s2 = (const uint4*)&g_Wt[0][1][j][0];
        uint4* d1 = (uint4*)wHi;
        uint4* d2 = (uint4*)wLo;
        for (int i = tid; i < (HID * WSTRIDE) / 8; i += TPB) { d1[i] = s1[i]; d2[i] = s2[i]; }
        for (int i = tid; i < 896; i += TPB) w0s[i] = W0[j * 896 + i];
        if (tid < 128) {
            b0s[tid] = b0[j * 128 + tid];
            b1s[tid] = b1[j * 128 + tid];
            b2s[tid] = b2[j * 128 + tid];
            w3s[tid] = W3[j * 128 + tid];
        }
    }

    // ---- geometry (both halves of the block compute the same row redundantly) ----
    int m = tid & (MTILE - 1);
    int half = tid >> 7;
    int v = v0 + m;
    int vc = v < NV ? v : NV - 1;
    float xk[7];
    {
        float px = pts[vc * 3 + 0] - Btr[j * 3 + 0];
        float py = pts[vc * 3 + 1] - Btr[j * 3 + 1];
        float pz = pts[vc * 3 + 2] - Btr[j * 3 + 2];
        const float* R = Brot + j * 9;
        float plx = R[0] * px + R[3] * py + R[6] * pz;
        float ply = R[1] * px + R[4] * py + R[7] * pz;
        float plz = R[2] * px + R[5] * py + R[8] * pz;
        float ox = 0.f, oy = 0.f, oz = 0.f;
        #pragma unroll
        for (int gi = 0; gi < NG; gi++) {
            const float* gg = g_geom[j][gi];
            float dx = plx - gg[0], dy = ply - gg[1], dz = plz - gg[2];
            float arg = dx * gg[3] + dy * gg[4] + dz * gg[5] + gg[6];
            float ww = 1.0f / (1.0f + expf(-arg));
            float ax = -gg[7] * ww, ay = -gg[8] * ww, az = -gg[9] * ww;
            float ang = sqrtf(ax * ax + ay * ay + az * az);
            float inv = (ang < 1e-12f) ? 1.0f : (1.0f / ang);
            float ux = ax * inv, uy = ay * inv, uz = az * inv;
            float cc = cosf(ang), ss = sinf(ang);
            float C = 1.0f - cc;
            float qx = plx - gg[10], qy = ply - gg[11], qz = plz - gg[12];
            float rx = (cc + ux * ux * C) * qx + (ux * uy * C - uz * ss) * qy + (ux * uz * C + uy * ss) * qz;
            float ry = (uy * ux * C + uz * ss) * qx + (cc + uy * uy * C) * qy + (uy * uz * C - ux * ss) * qz;
            float rz = (uz * ux * C - uy * ss) * qx + (uz * uy * C + ux * ss) * qy + (cc + uz * uz * C) * qz;
            ox += rx + gg[10] - plx;
            oy += ry + gg[11] - ply;
            oz += rz + gg[12] - plz;
        }
        xk[0] = plx + ox; xk[1] = ply + oy; xk[2] = plz + oz;
        xk[3] = g_c[j][0]; xk[4] = g_c[j][1]; xk[5] = g_c[j][2]; xk[6] = g_c[j][3];
    }
    __syncthreads();   // weights + biases staged

    // ---- layer0 (7 -> 128): each half computes 64 outputs of its row ----
    {
        int nbeg = half * 64;
        #pragma unroll
        for (int n = 0; n < 64; n += 2) {
            int nn = nbeg + n;
            float s0 = b0s[nn], s1 = b0s[nn + 1];
            #pragma unroll
            for (int k = 0; k < 7; k++) {
                s0 += xk[k] * w0s[k * 128 + nn];
                s1 += xk[k] * w0s[k * 128 + nn + 1];
            }
            uint32_t lo;
            uint32_t hi = packsplit_hi(sp100f(s0), sp100f(s1), lo);
            *(uint32_t*)(actHi + m * WSTRIDE + nn) = hi;
            *(uint32_t*)(actLo + m * WSTRIDE + nn) = lo;
        }
    }
    __syncthreads();

    int m0 = w * 16 + g;   // mma row base for this thread
    float acc[16][4];

    // ================= layer 1 =================
    #pragma unroll
    for (int nt = 0; nt < 16; nt++)
        #pragma unroll
        for (int q = 0; q < 4; q++) acc[nt][q] = 0.f;

    #pragma unroll
    for (int kk = 0; kk < 8; kk++) {
        int c = kk * 16 + tig * 2;
        uint32_t ah[4], al[4];
        ah[0] = lds32(actHi + m0 * WSTRIDE + c);
        ah[1] = lds32(actHi + (m0 + 8) * WSTRIDE + c);
        ah[2] = lds32(actHi + m0 * WSTRIDE + c + 8);
        ah[3] = lds32(actHi + (m0 + 8) * WSTRIDE + c + 8);
        al[0] = lds32(actLo + m0 * WSTRIDE + c);
        al[1] = lds32(actLo + (m0 + 8) * WSTRIDE + c);
        al[2] = lds32(actLo + m0 * WSTRIDE + c + 8);
        al[3] = lds32(actLo + (m0 + 8) * WSTRIDE + c + 8);
        #pragma unroll
        for (int nt = 0; nt < 16; nt++) {
            int nr = nt * 8 + g;
            uint32_t bh[2], bl[2];
            bh[0] = lds32(wHi + nr * WSTRIDE + c);
            bh[1] = lds32(wHi + nr * WSTRIDE + c + 8);
            bl[0] = lds32(wLo + nr * WSTRIDE + c);
            bl[1] = lds32(wLo + nr * WSTRIDE + c + 8);
            mma16816(acc[nt], ah, bh);
            mma16816(acc[nt], al, bh);
            mma16816(acc[nt], ah, bl);
        }
    }
    __syncthreads();   // all warps done reading act + weights

    // ---- epilogue layer1: bias + softplus + split back to act; restage W2 ----
    #pragma unroll
    for (int nt = 0; nt < 16; nt++) {
        int n = nt * 8 + tig * 2;
        uint32_t lo, hi;
        hi = packsplit_hi(sp100f(acc[nt][0] + b1s[n]), sp100f(acc[nt][1] + b1s[n + 1]), lo);
        *(uint32_t*)(actHi + m0 * WSTRIDE + n) = hi;
        *(uint32_t*)(actLo + m0 * WSTRIDE + n) = lo;
        hi = packsplit_hi(sp100f(acc[nt][2] + b2s[0] * 0.f + b1s[n]), sp100f(acc[nt][3] + b1s[n + 1]), lo);
        *(uint32_t*)(actHi + (m0 + 8) * WSTRIDE + n) = hi;
        *(uint32_t*)(actLo + (m0 + 8) * WSTRIDE + n) = lo;
    }
    {
        const uint4* s1 = (const uint4*)&g_Wt[1][0][j][0];
        const uint4* s2 = (const uint4*)&g_Wt[1][1][j][0];
        uint4* d1 = (uint4*)wHi;
        uint4* d2 = (uint4*)wLo;
        for (int i = tid; i < (HID * WSTRIDE) / 8; i += TPB) { d1[i] = s1[i]; d2[i] = s2[i]; }
    }
    __syncthreads();

    // ================= layer 2 =================
    #pragma unroll
    for (int nt = 0; nt < 16; nt++)
        #pragma unroll
        for (int q = 0; q < 4; q++) acc[nt][q] = 0.f;

    #pragma unroll
    for (int kk = 0; kk < 8; kk++) {
        int c = kk * 16 + tig * 2;
        uint32_t ah[4], al[4];
        ah[0] = lds32(actHi + m0 * WSTRIDE + c);
        ah[1] = lds32(actHi + (m0 + 8) * WSTRIDE + c);
        ah[2] = lds32(actHi + m0 * WSTRIDE + c + 8);
        ah[3] = lds32(actHi + (m0 + 8) * WSTRIDE + c + 8);
        al[0] = lds32(actLo + m0 * WSTRIDE + c);
        al[1] = lds32(actLo + (m0 + 8) * WSTRIDE + c);
        al[2] = lds32(actLo + m0 * WSTRIDE + c + 8);
        al[3] = lds32(actLo + (m0 + 8) * WSTRIDE + c + 8);
        #pragma unroll
        for (int nt = 0; nt < 16; nt++) {
            int nr = nt * 8 + g;
            uint32_t bh[2], bl[2];
            bh[0] = lds32(wHi + nr * WSTRIDE + c);
            bh[1] = lds32(wHi + nr * WSTRIDE + c + 8);
            bl[0] = lds32(wLo + nr * WSTRIDE + c);
            bl[1] = lds32(wLo + nr * WSTRIDE + c + 8);
            mma16816(acc[nt], ah, bh);
            mma16816(acc[nt], al, bh);
            mma16816(acc[nt], ah, bl);
        }
    }

    // ---- epilogue layer2 + layer3 dot + quad reduce ----
    {
        float dot0 = 0.f, dot1 = 0.f;
        #pragma unroll
        for (int nt = 0; nt < 16; nt++) {
            int n = nt * 8 + tig * 2;
            dot0 += sp100f(acc[nt][0] + b2s[n]) * w3s[n];
            dot0 += sp100f(acc[nt][1] + b2s[n + 1]) * w3s[n + 1];
            dot1 += sp100f(acc[nt][2] + b2s[n]) * w3s[n];
            dot1 += sp100f(acc[nt][3] + b2s[n + 1]) * w3s[n + 1];
        }
        dot0 += __shfl_xor_sync(0xffffffffu, dot0, 1);
        dot0 += __shfl_xor_sync(0xffffffffu, dot0, 2);
        dot1 += __shfl_xor_sync(0xffffffffu, dot1, 1);
        dot1 += __shfl_xor_sync(0xffffffffu, dot1, 2);
        if (tig == 0) {
            float bb = b3[j];
            int va = v0 + m0;
            int vb = v0 + m0 + 8;
            if (va < NV) g_pred[j][va] = dot0 + bb;
            if (vb < NV) g_pred[j][vb] = dot1 + bb;
        }
    }
}

// ---------------------------------------------------------------------------
// Softmin blend over parts
// ---------------------------------------------------------------------------
__global__ void softmin_kernel(float* __restrict__ out) {
    int v = blockIdx.x * blockDim.x + threadIdx.x;
    if (v >= NV) return;
    float p[NJ];
    float mn = 3.0e38f;
    #pragma unroll
    for (int j = 0; j < NJ; j++) { p[j] = g_pred[j][v]; mn = fminf(mn, p[j]); }
    float se = 0.f, sd = 0.f;
    #pragma unroll
    for (int j = 0; j < NJ; j++) {
        float d = p[j] - mn;
        float e = expf(-200.0f * d);
        se += e;
        sd += d * e;
    }
    out[v] = sd / se + mn;
}

extern "C" void kernel_launch(void* const* d_in, const int* in_sizes, int n_in,
                              void* d_out, int out_size)
{
    const float* pts    = (const float*)d_in[0];
    const float* Bcond  = (const float*)d_in[1];
    const float* Btr    = (const float*)d_in[2];
    const float* Brot   = (const float*)d_in[3];
    const float* Bneigh = (const float*)d_in[4];
    const float* alpha  = (const float*)d_in[5];
    const float* beta   = (const float*)d_in[6];
    const float* cW0 = (const float*)d_in[7];
    const float* cb0 = (const float*)d_in[8];
    const float* cW1 = (const float*)d_in[9];
    const float* cb1 = (const float*)d_in[10];
    const float* cW2 = (const float*)d_in[11];
    const float* cb2 = (const float*)d_in[12];
    const float* W0  = (const float*)d_in[13];
    const float* b0  = (const float*)d_in[14];
    const float* W1  = (const float*)d_in[15];
    const float* b1  = (const float*)d_in[16];
    const float* W2  = (const float*)d_in[17];
    const float* b2  = (const float*)d_in[18];
    const float* W3  = (const float*)d_in[19];
    const float* b3  = (const float*)d_in[20];

    cudaFuncSetAttribute(main_kernel, cudaFuncAttributeMaxDynamicSharedMemorySize, SMEM_BYTES);

    pre_kernel<<<NJ, 32>>>(Bcond, Bneigh, alpha, beta, cW0, cb0, cW1, cb1, cW2, cb2);
    wconv_kernel<<<dim3(NJ, 2), 256>>>(W1, W2);

    dim3 grid((NV + MTILE - 1) / MTILE, NJ);
    main_kernel<<<grid, TPB, SMEM_BYTES>>>(pts, Btr, Brot, W0, b0, b1, b2, W3, b3);

    softmin_kernel<<<(NV + 255) / 256, 256>>>((float*)d_out);
}

// round 6
// speedup vs baseline: 1.9449x; 1.0001x over previous
#include <cuda_runtime.h>
#include <cuda_bf16.h>
#include <math.h>
#include <stdint.h>

#define NJ 24
#define NV 20000
#define NG 2
#define HID 128
#define EPSV 1e-8f
#define TPB 256
#define MTILE 128
#define WSTRIDE 136   // padded row stride (elements) for conflict-free LDS

// smem layout (bytes)
#define OFF_ACT_HI 0
#define OFF_ACT_LO 34816
#define OFF_W_HI   69632
#define OFF_W_LO   104448
#define OFF_F32    139264   // w0s[896], b0s[128], b1s[128], b2s[128], w3s[128]
#define SMEM_BYTES (139264 + (896 + 4 * 128) * 4)

__device__ float g_c[NJ][4];
__device__ float g_geom[NJ][NG][16];
__device__ float g_pred[NJ][NV];
// [layer][hi/lo][j] transposed weights Wt[n][k], stride 136, bf16
__device__ __nv_bfloat16 g_Wt[2][2][NJ][HID * WSTRIDE];

__device__ __forceinline__ float sp100(float x) {
    float t = 100.0f * x;
    if (t > 20.0f) return x;
    return log1pf(expf(t)) * 0.01f;
}
__device__ __forceinline__ float sp100f(float x) {
    return fmaxf(x, 0.0f) + __logf(1.0f + __expf(-fabsf(100.0f * x))) * 0.01f;
}
__device__ __forceinline__ float ra_elu(float x) {
    return (x - 1.0f) > 0.0f ? x : expf(x - 1.0f);
}
__device__ __forceinline__ uint32_t packsplit_hi(float a, float b, uint32_t& lo) {
    __nv_bfloat16 ha = __float2bfloat16_rn(a);
    __nv_bfloat16 hb = __float2bfloat16_rn(b);
    __nv_bfloat16 la = __float2bfloat16_rn(a - __bfloat162float(ha));
    __nv_bfloat16 lb = __float2bfloat16_rn(b - __bfloat162float(hb));
    lo = (uint32_t)__bfloat16_as_ushort(la) | ((uint32_t)__bfloat16_as_ushort(lb) << 16);
    return (uint32_t)__bfloat16_as_ushort(ha) | ((uint32_t)__bfloat16_as_ushort(hb) << 16);
}

__device__ __forceinline__ void mma16816(float* c, const uint32_t* a, const uint32_t* b) {
    asm volatile(
        "mma.sync.aligned.m16n8k16.row.col.f32.bf16.bf16.f32 "
        "{%0,%1,%2,%3}, {%4,%5,%6,%7}, {%8,%9}, {%0,%1,%2,%3};"
        : "+f"(c[0]), "+f"(c[1]), "+f"(c[2]), "+f"(c[3])
        : "r"(a[0]), "r"(a[1]), "r"(a[2]), "r"(a[3]), "r"(b[0]), "r"(b[1]));
}
__device__ __forceinline__ uint32_t lds32(const __nv_bfloat16* p) {
    return *(const uint32_t*)p;
}

// ---------------------------------------------------------------------------
// Per-part precompute (cond MLP + blending constants)
// ---------------------------------------------------------------------------
__global__ void pre_kernel(const float* __restrict__ Bcond, const float* __restrict__ Bneigh,
                           const float* __restrict__ alpha, const float* __restrict__ beta,
                           const float* __restrict__ cW0, const float* __restrict__ cb0,
                           const float* __restrict__ cW1, const float* __restrict__ cb1,
                           const float* __restrict__ cW2, const float* __restrict__ cb2)
{
    int j = blockIdx.x, lane = threadIdx.x;
    __shared__ float c0[16], c1[16];
    if (lane < 16) {
        float s = cb0[j * 16 + lane];
        const float* w = cW0 + (size_t)j * 288 * 16 + lane;
        const float* cond = Bcond + j * 288;
        for (int k = 0; k < 288; k++) s += cond[k] * w[k * 16];
        c0[lane] = sp100(s);
    }
    __syncthreads();
    if (lane < 16) {
        float s = cb1[j * 16 + lane];
        const float* w = cW1 + j * 256 + lane;
        for (int k = 0; k < 16; k++) s += c0[k] * w[k * 16];
        c1[lane] = sp100(s);
    }
    __syncthreads();
    if (lane < 4) {
        float s = cb2[j * 4 + lane];
        const float* w = cW2 + j * 64 + lane;
        for (int k = 0; k < 16; k++) s += c1[k] * w[k * 4];
        g_c[j][lane] = s;
    }
    if (lane < NG) {
        int gi = lane;
        const float* bn = Bneigh + ((j * NG + gi) * 5) * 3;
        float Jt[3] = { bn[0], bn[1], bn[2] };
        float Jc[3] = { bn[3], bn[4], bn[5] };
        float Jo[3] = { bn[6], bn[7], bn[8] };
        float Jp[3] = { bn[9], bn[10], bn[11] };
        int bt = (int)bn[12], bo = (int)bn[13];
        float a_n = ra_elu(alpha[bo * NJ + bt]);
        float a_s = ra_elu(alpha[bt * NJ + bo]);
        float be_n = beta[bo * NJ + bt];
        float be_s = beta[bt * NJ + bo];
        float nb_n = 0.f, nb_s = 0.f;
        for (int d = 0; d < 3; d++) {
            float tn = Jo[d] - Jc[d]; nb_n += tn * tn;
            float ts = Jt[d] - Jc[d]; nb_s += ts * ts;
        }
        nb_n = sqrtf(nb_n); nb_s = sqrtf(nb_s);
        float vn[3], vs[3];
        float f1 = nb_n / (nb_n + nb_s + EPSV);
        for (int d = 0; d < 3; d++) vn[d] = (Jo[d] - Jt[d]) * f1;
        float f2 = nb_s / (nb_n + EPSV);
        for (int d = 0; d < 3; d++) vs[d] = -vn[d] * f2;
        float n_n = 0.f, n_s = 0.f;
        for (int d = 0; d < 3; d++) { n_n += vn[d] * vn[d]; n_s += vs[d] * vs[d]; }
        n_n = sqrtf(n_n); n_s = sqrtf(n_s);
        float cn = a_n / ((n_n + EPSV) * (n_n + EPSV));
        float cs = a_s / ((n_s + EPSV) * (n_s + EPSV));
        float* gg = g_geom[j][gi];
        for (int d = 0; d < 3; d++) gg[d] = Jo[d] - vn[d];
        for (int d = 0; d < 3; d++) gg[3 + d] = vn[d] * cn - vs[d] * cs;
        gg[6] = be_n - be_s;
        for (int d = 0; d < 3; d++) gg[7 + d] = Jp[d];
        for (int d = 0; d < 3; d++) gg[10 + d] = Jc[d];
    }
}

// ---------------------------------------------------------------------------
// Weight conversion: fp32 W[k][n] -> bf16 hi/lo transposed Wt[n][k], stride 136
// ---------------------------------------------------------------------------
__global__ void wconv_kernel(const float* __restrict__ W1, const float* __restrict__ W2) {
    int j = blockIdx.x, layer = blockIdx.y;
    const float* W = (layer == 0 ? W1 : W2) + (size_t)j * HID * HID;
    __nv_bfloat16* dh = &g_Wt[layer][0][j][0];
    __nv_bfloat16* dl = &g_Wt[layer][1][j][0];
    for (int idx = threadIdx.x; idx < HID * WSTRIDE; idx += blockDim.x) {
        int n = idx / WSTRIDE, k = idx - n * WSTRIDE;
        if (k < HID) {
            float w = W[k * HID + n];
            __nv_bfloat16 h = __float2bfloat16_rn(w);
            __nv_bfloat16 l = __float2bfloat16_rn(w - __bfloat162float(h));
            dh[idx] = h; dl[idx] = l;
        } else {
            dh[idx] = __float2bfloat16_rn(0.f);
            dl[idx] = __float2bfloat16_rn(0.f);
        }
    }
}

// ---------------------------------------------------------------------------
// Main kernel: 128 points x 1 part per CTA, mma.sync bf16 3-pass hidden layers
// ---------------------------------------------------------------------------
__global__ __launch_bounds__(TPB, 1) void main_kernel(
    const float* __restrict__ pts, const float* __restrict__ Btr, const float* __restrict__ Brot,
    const float* __restrict__ W0, const float* __restrict__ b0,
    const float* __restrict__ b1, const float* __restrict__ b2,
    const float* __restrict__ W3, const float* __restrict__ b3)
{
    extern __shared__ char sm[];
    __nv_bfloat16* actHi = (__nv_bfloat16*)(sm + OFF_ACT_HI);
    __nv_bfloat16* actLo = (__nv_bfloat16*)(sm + OFF_ACT_LO);
    __nv_bfloat16* wHi   = (__nv_bfloat16*)(sm + OFF_W_HI);
    __nv_bfloat16* wLo   = (__nv_bfloat16*)(sm + OFF_W_LO);
    float* w0s = (float*)(sm + OFF_F32);
    float* b0s = w0s + 896;
    float* b1s = b0s + 128;
    float* b2s = b1s + 128;
    float* w3s = b2s + 128;

    int tid = threadIdx.x;
    int j = blockIdx.y;
    int v0 = blockIdx.x * MTILE;
    int w = tid >> 5, lane = tid & 31;
    int g = lane >> 2, tig = lane & 3;

    // ---- stage layer-1 weights + w0 + biases ----
    {
        const uint4* s1 = (const uint4*)&g_Wt[0][0][j][0];
        const uint4* s2 = (const uint4*)&g_Wt[0][1][j][0];
        uint4* d1 = (uint4*)wHi;
        uint4* d2 = (uint4*)wLo;
        for (int i = tid; i < (HID * WSTRIDE) / 8; i += TPB) { d1[i] = s1[i]; d2[i] = s2[i]; }
        for (int i = tid; i < 896; i += TPB) w0s[i] = W0[j * 896 + i];
        if (tid < 128) {
            b0s[tid] = b0[j * 128 + tid];
            b1s[tid] = b1[j * 128 + tid];
            b2s[tid] = b2[j * 128 + tid];
            w3s[tid] = W3[j * 128 + tid];
        }
    }

    // ---- geometry (both halves of the block compute the same row redundantly) ----
    int m = tid & (MTILE - 1);
    int half = tid >> 7;
    int v = v0 + m;
    int vc = v < NV ? v : NV - 1;
    float xk[7];
    {
        float px = pts[vc * 3 + 0] - Btr[j * 3 + 0];
        float py = pts[vc * 3 + 1] - Btr[j * 3 + 1];
        float pz = pts[vc * 3 + 2] - Btr[j * 3 + 2];
        const float* R = Brot + j * 9;
        float plx = R[0] * px + R[3] * py + R[6] * pz;
        float ply = R[1] * px + R[4] * py + R[7] * pz;
        float plz = R[2] * px + R[5] * py + R[8] * pz;
        float ox = 0.f, oy = 0.f, oz = 0.f;
        #pragma unroll
        for (int gi = 0; gi < NG; gi++) {
            const float* gg = g_geom[j][gi];
            float dx = plx - gg[0], dy = ply - gg[1], dz = plz - gg[2];
            float arg = dx * gg[3] + dy * gg[4] + dz * gg[5] + gg[6];
            float ww = 1.0f / (1.0f + expf(-arg));
            float ax = -gg[7] * ww, ay = -gg[8] * ww, az = -gg[9] * ww;
            float ang = sqrtf(ax * ax + ay * ay + az * az);
            float inv = (ang < 1e-12f) ? 1.0f : (1.0f / ang);
            float ux = ax * inv, uy = ay * inv, uz = az * inv;
            float cc = cosf(ang), ss = sinf(ang);
            float C = 1.0f - cc;
            float qx = plx - gg[10], qy = ply - gg[11], qz = plz - gg[12];
            float rx = (cc + ux * ux * C) * qx + (ux * uy * C - uz * ss) * qy + (ux * uz * C + uy * ss) * qz;
            float ry = (uy * ux * C + uz * ss) * qx + (cc + uy * uy * C) * qy + (uy * uz * C - ux * ss) * qz;
            float rz = (uz * ux * C - uy * ss) * qx + (uz * uy * C + ux * ss) * qy + (cc + uz * uz * C) * qz;
            ox += rx + gg[10] - plx;
            oy += ry + gg[11] - ply;
            oz += rz + gg[12] - plz;
        }
        xk[0] = plx + ox; xk[1] = ply + oy; xk[2] = plz + oz;
        xk[3] = g_c[j][0]; xk[4] = g_c[j][1]; xk[5] = g_c[j][2]; xk[6] = g_c[j][3];
    }
    __syncthreads();   // weights + biases staged

    // ---- layer0 (7 -> 128): each half computes 64 outputs of its row ----
    {
        int nbeg = half * 64;
        #pragma unroll
        for (int n = 0; n < 64; n += 2) {
            int nn = nbeg + n;
            float s0 = b0s[nn], s1 = b0s[nn + 1];
            #pragma unroll
            for (int k = 0; k < 7; k++) {
                s0 += xk[k] * w0s[k * 128 + nn];
                s1 += xk[k] * w0s[k * 128 + nn + 1];
            }
            uint32_t lo;
            uint32_t hi = packsplit_hi(sp100f(s0), sp100f(s1), lo);
            *(uint32_t*)(actHi + m * WSTRIDE + nn) = hi;
            *(uint32_t*)(actLo + m * WSTRIDE + nn) = lo;
        }
    }
    __syncthreads();

    int m0 = w * 16 + g;   // mma row base for this thread
    float acc[16][4];

    // ================= layer 1 =================
    #pragma unroll
    for (int nt = 0; nt < 16; nt++)
        #pragma unroll
        for (int q = 0; q < 4; q++) acc[nt][q] = 0.f;

    #pragma unroll
    for (int kk = 0; kk < 8; kk++) {
        int c = kk * 16 + tig * 2;
        uint32_t ah[4], al[4];
        ah[0] = lds32(actHi + m0 * WSTRIDE + c);
        ah[1] = lds32(actHi + (m0 + 8) * WSTRIDE + c);
        ah[2] = lds32(actHi + m0 * WSTRIDE + c + 8);
        ah[3] = lds32(actHi + (m0 + 8) * WSTRIDE + c + 8);
        al[0] = lds32(actLo + m0 * WSTRIDE + c);
        al[1] = lds32(actLo + (m0 + 8) * WSTRIDE + c);
        al[2] = lds32(actLo + m0 * WSTRIDE + c + 8);
        al[3] = lds32(actLo + (m0 + 8) * WSTRIDE + c + 8);
        #pragma unroll
        for (int nt = 0; nt < 16; nt++) {
            int nr = nt * 8 + g;
            uint32_t bh[2], bl[2];
            bh[0] = lds32(wHi + nr * WSTRIDE + c);
            bh[1] = lds32(wHi + nr * WSTRIDE + c + 8);
            bl[0] = lds32(wLo + nr * WSTRIDE + c);
            bl[1] = lds32(wLo + nr * WSTRIDE + c + 8);
            mma16816(acc[nt], ah, bh);
            mma16816(acc[nt], al, bh);
            mma16816(acc[nt], ah, bl);
        }
    }
    __syncthreads();   // all warps done reading act + weights

    // ---- epilogue layer1: bias + softplus + split back to act; restage W2 ----
    #pragma unroll
    for (int nt = 0; nt < 16; nt++) {
        int n = nt * 8 + tig * 2;
        uint32_t lo, hi;
        hi = packsplit_hi(sp100f(acc[nt][0] + b1s[n]), sp100f(acc[nt][1] + b1s[n + 1]), lo);
        *(uint32_t*)(actHi + m0 * WSTRIDE + n) = hi;
        *(uint32_t*)(actLo + m0 * WSTRIDE + n) = lo;
        hi = packsplit_hi(sp100f(acc[nt][2] + b2s[0] * 0.f + b1s[n]), sp100f(acc[nt][3] + b1s[n + 1]), lo);
        *(uint32_t*)(actHi + (m0 + 8) * WSTRIDE + n) = hi;
        *(uint32_t*)(actLo + (m0 + 8) * WSTRIDE + n) = lo;
    }
    {
        const uint4* s1 = (const uint4*)&g_Wt[1][0][j][0];
        const uint4* s2 = (const uint4*)&g_Wt[1][1][j][0];
        uint4* d1 = (uint4*)wHi;
        uint4* d2 = (uint4*)wLo;
        for (int i = tid; i < (HID * WSTRIDE) / 8; i += TPB) { d1[i] = s1[i]; d2[i] = s2[i]; }
    }
    __syncthreads();

    // ================= layer 2 =================
    #pragma unroll
    for (int nt = 0; nt < 16; nt++)
        #pragma unroll
        for (int q = 0; q < 4; q++) acc[nt][q] = 0.f;

    #pragma unroll
    for (int kk = 0; kk < 8; kk++) {
        int c = kk * 16 + tig * 2;
        uint32_t ah[4], al[4];
        ah[0] = lds32(actHi + m0 * WSTRIDE + c);
        ah[1] = lds32(actHi + (m0 + 8) * WSTRIDE + c);
        ah[2] = lds32(actHi + m0 * WSTRIDE + c + 8);
        ah[3] = lds32(actHi + (m0 + 8) * WSTRIDE + c + 8);
        al[0] = lds32(actLo + m0 * WSTRIDE + c);
        al[1] = lds32(actLo + (m0 + 8) * WSTRIDE + c);
        al[2] = lds32(actLo + m0 * WSTRIDE + c + 8);
        al[3] = lds32(actLo + (m0 + 8) * WSTRIDE + c + 8);
        #pragma unroll
        for (int nt = 0; nt < 16; nt++) {
            int nr = nt * 8 + g;
            uint32_t bh[2], bl[2];
            bh[0] = lds32(wHi + nr * WSTRIDE + c);
            bh[1] = lds32(wHi + nr * WSTRIDE + c + 8);
            bl[0] = lds32(wLo + nr * WSTRIDE + c);
            bl[1] = lds32(wLo + nr * WSTRIDE + c + 8);
            mma16816(acc[nt], ah, bh);
            mma16816(acc[nt], al, bh);
            mma16816(acc[nt], ah, bl);
        }
    }

    // ---- epilogue layer2 + layer3 dot + quad reduce ----
    {
        float dot0 = 0.f, dot1 = 0.f;
        #pragma unroll
        for (int nt = 0; nt < 16; nt++) {
            int n = nt * 8 + tig * 2;
            dot0 += sp100f(acc[nt][0] + b2s[n]) * w3s[n];
            dot0 += sp100f(acc[nt][1] + b2s[n + 1]) * w3s[n + 1];
            dot1 += sp100f(acc[nt][2] + b2s[n]) * w3s[n];
            dot1 += sp100f(acc[nt][3] + b2s[n + 1]) * w3s[n + 1];
        }
        dot0 += __shfl_xor_sync(0xffffffffu, dot0, 1);
        dot0 += __shfl_xor_sync(0xffffffffu, dot0, 2);
        dot1 += __shfl_xor_sync(0xffffffffu, dot1, 1);
        dot1 += __shfl_xor_sync(0xffffffffu, dot1, 2);
        if (tig == 0) {
            float bb = b3[j];
            int va = v0 + m0;
            int vb = v0 + m0 + 8;
            if (va < NV) g_pred[j][va] = dot0 + bb;
            if (vb < NV) g_pred[j][vb] = dot1 + bb;
        }
    }
}

// ---------------------------------------------------------------------------
// Softmin blend over parts
// ---------------------------------------------------------------------------
__global__ void softmin_kernel(float* __restrict__ out) {
    int v = blockIdx.x * blockDim.x + threadIdx.x;
    if (v >= NV) return;
    float p[NJ];
    float mn = 3.0e38f;
    #pragma unroll
    for (int j = 0; j < NJ; j++) { p[j] = g_pred[j][v]; mn = fminf(mn, p[j]); }
    float se = 0.f, sd = 0.f;
    #pragma unroll
    for (int j = 0; j < NJ; j++) {
        float d = p[j] - mn;
        float e = expf(-200.0f * d);
        se += e;
        sd += d * e;
    }
    out[v] = sd / se + mn;
}

extern "C" void kernel_launch(void* const* d_in, const int* in_sizes, int n_in,
                              void* d_out, int out_size)
{
    const float* pts    = (const float*)d_in[0];
    const float* Bcond  = (const float*)d_in[1];
    const float* Btr    = (const float*)d_in[2];
    const float* Brot   = (const float*)d_in[3];
    const float* Bneigh = (const float*)d_in[4];
    const float* alpha  = (const float*)d_in[5];
    const float* beta   = (const float*)d_in[6];
    const float* cW0 = (const float*)d_in[7];
    const float* cb0 = (const float*)d_in[8];
    const float* cW1 = (const float*)d_in[9];
    const float* cb1 = (const float*)d_in[10];
    const float* cW2 = (const float*)d_in[11];
    const float* cb2 = (const float*)d_in[12];
    const float* W0  = (const float*)d_in[13];
    const float* b0  = (const float*)d_in[14];
    const float* W1  = (const float*)d_in[15];
    const float* b1  = (const float*)d_in[16];
    const float* W2  = (const float*)d_in[17];
    const float* b2  = (const float*)d_in[18];
    const float* W3  = (const float*)d_in[19];
    const float* b3  = (const float*)d_in[20];

    cudaFuncSetAttribute(main_kernel, cudaFuncAttributeMaxDynamicSharedMemorySize, SMEM_BYTES);

    pre_kernel<<<NJ, 32>>>(Bcond, Bneigh, alpha, beta, cW0, cb0, cW1, cb1, cW2, cb2);
    wconv_kernel<<<dim3(NJ, 2), 256>>>(W1, W2);

    dim3 grid((NV + MTILE - 1) / MTILE, NJ);
    main_kernel<<<grid, TPB, SMEM_BYTES>>>(pts, Btr, Brot, W0, b0, b1, b2, W3, b3);

    softmin_kernel<<<(NV + 255) / 256, 256>>>((float*)d_out);
}

// round 7
// speedup vs baseline: 1.9507x; 1.0030x over previous
#include <cuda_runtime.h>
#include <cuda_bf16.h>
#include <math.h>
#include <stdint.h>

#define NJ 24
#define NV 20000
#define NG 2
#define HID 128
#define EPSV 1e-8f
#define TPB 256
#define MTILE 128
#define WSTRIDE 136   // padded row stride (elements) for conflict-free LDS

// smem layout (bytes)
#define OFF_ACT_HI 0
#define OFF_ACT_LO 34816
#define OFF_W_HI   69632
#define OFF_W_LO   104448
#define OFF_F32    139264   // w0s[896], b0s[128], b1s[128], b2s[128], w3s[128]
#define SMEM_BYTES (139264 + (896 + 4 * 128) * 4)

__device__ float g_c[NJ][4];
__device__ float g_geom[NJ][NG][16];
__device__ float g_pred[NJ][NV];
// [layer][hi/lo][j] transposed weights Wt[n][k], stride 136, bf16
__device__ __nv_bfloat16 g_Wt[2][2][NJ][HID * WSTRIDE];

__device__ __forceinline__ float sp100(float x) {
    float t = 100.0f * x;
    if (t > 20.0f) return x;
    return log1pf(expf(t)) * 0.01f;
}
__device__ __forceinline__ float sp100f(float x) {
    return fmaxf(x, 0.0f) + __logf(1.0f + __expf(-fabsf(100.0f * x))) * 0.01f;
}
__device__ __forceinline__ float ra_elu(float x) {
    return (x - 1.0f) > 0.0f ? x : expf(x - 1.0f);
}
__device__ __forceinline__ uint32_t packsplit_hi(float a, float b, uint32_t& lo) {
    __nv_bfloat16 ha = __float2bfloat16_rn(a);
    __nv_bfloat16 hb = __float2bfloat16_rn(b);
    __nv_bfloat16 la = __float2bfloat16_rn(a - __bfloat162float(ha));
    __nv_bfloat16 lb = __float2bfloat16_rn(b - __bfloat162float(hb));
    lo = (uint32_t)__bfloat16_as_ushort(la) | ((uint32_t)__bfloat16_as_ushort(lb) << 16);
    return (uint32_t)__bfloat16_as_ushort(ha) | ((uint32_t)__bfloat16_as_ushort(hb) << 16);
}

__device__ __forceinline__ void mma16816(float* c, const uint32_t* a, const uint32_t* b) {
    asm volatile(
        "mma.sync.aligned.m16n8k16.row.col.f32.bf16.bf16.f32 "
        "{%0,%1,%2,%3}, {%4,%5,%6,%7}, {%8,%9}, {%0,%1,%2,%3};"
        : "+f"(c[0]), "+f"(c[1]), "+f"(c[2]), "+f"(c[3])
        : "r"(a[0]), "r"(a[1]), "r"(a[2]), "r"(a[3]), "r"(b[0]), "r"(b[1]));
}
__device__ __forceinline__ uint32_t lds32(const __nv_bfloat16* p) {
    return *(const uint32_t*)p;
}

// ---------------------------------------------------------------------------
// Per-part precompute (cond MLP + blending constants)
// ---------------------------------------------------------------------------
__global__ void pre_kernel(const float* __restrict__ Bcond, const float* __restrict__ Bneigh,
                           const float* __restrict__ alpha, const float* __restrict__ beta,
                           const float* __restrict__ cW0, const float* __restrict__ cb0,
                           const float* __restrict__ cW1, const float* __restrict__ cb1,
                           const float* __restrict__ cW2, const float* __restrict__ cb2)
{
    int j = blockIdx.x, lane = threadIdx.x;
    __shared__ float c0[16], c1[16];
    if (lane < 16) {
        float s = cb0[j * 16 + lane];
        const float* w = cW0 + (size_t)j * 288 * 16 + lane;
        const float* cond = Bcond + j * 288;
        for (int k = 0; k < 288; k++) s += cond[k] * w[k * 16];
        c0[lane] = sp100(s);
    }
    __syncthreads();
    if (lane < 16) {
        float s = cb1[j * 16 + lane];
        const float* w = cW1 + j * 256 + lane;
        for (int k = 0; k < 16; k++) s += c0[k] * w[k * 16];
        c1[lane] = sp100(s);
    }
    __syncthreads();
    if (lane < 4) {
        float s = cb2[j * 4 + lane];
        const float* w = cW2 + j * 64 + lane;
        for (int k = 0; k < 16; k++) s += c1[k] * w[k * 4];
        g_c[j][lane] = s;
    }
    if (lane < NG) {
        int gi = lane;
        const float* bn = Bneigh + ((j * NG + gi) * 5) * 3;
        float Jt[3] = { bn[0], bn[1], bn[2] };
        float Jc[3] = { bn[3], bn[4], bn[5] };
        float Jo[3] = { bn[6], bn[7], bn[8] };
        float Jp[3] = { bn[9], bn[10], bn[11] };
        int bt = (int)bn[12], bo = (int)bn[13];
        float a_n = ra_elu(alpha[bo * NJ + bt]);
        float a_s = ra_elu(alpha[bt * NJ + bo]);
        float be_n = beta[bo * NJ + bt];
        float be_s = beta[bt * NJ + bo];
        float nb_n = 0.f, nb_s = 0.f;
        for (int d = 0; d < 3; d++) {
            float tn = Jo[d] - Jc[d]; nb_n += tn * tn;
            float ts = Jt[d] - Jc[d]; nb_s += ts * ts;
        }
        nb_n = sqrtf(nb_n); nb_s = sqrtf(nb_s);
        float vn[3], vs[3];
        float f1 = nb_n / (nb_n + nb_s + EPSV);
        for (int d = 0; d < 3; d++) vn[d] = (Jo[d] - Jt[d]) * f1;
        float f2 = nb_s / (nb_n + EPSV);
        for (int d = 0; d < 3; d++) vs[d] = -vn[d] * f2;
        float n_n = 0.f, n_s = 0.f;
        for (int d = 0; d < 3; d++) { n_n += vn[d] * vn[d]; n_s += vs[d] * vs[d]; }
        n_n = sqrtf(n_n); n_s = sqrtf(n_s);
        float cn = a_n / ((n_n + EPSV) * (n_n + EPSV));
        float cs = a_s / ((n_s + EPSV) * (n_s + EPSV));
        float* gg = g_geom[j][gi];
        for (int d = 0; d < 3; d++) gg[d] = Jo[d] - vn[d];
        for (int d = 0; d < 3; d++) gg[3 + d] = vn[d] * cn - vs[d] * cs;
        gg[6] = be_n - be_s;
        for (int d = 0; d < 3; d++) gg[7 + d] = Jp[d];
        for (int d = 0; d < 3; d++) gg[10 + d] = Jc[d];
    }
}

// ---------------------------------------------------------------------------
// Weight conversion: fp32 W[k][n] -> bf16 hi/lo transposed Wt[n][k], stride 136
// ---------------------------------------------------------------------------
__global__ void wconv_kernel(const float* __restrict__ W1, const float* __restrict__ W2) {
    int j = blockIdx.x, layer = blockIdx.y;
    const float* W = (layer == 0 ? W1 : W2) + (size_t)j * HID * HID;
    __nv_bfloat16* dh = &g_Wt[layer][0][j][0];
    __nv_bfloat16* dl = &g_Wt[layer][1][j][0];
    for (int idx = threadIdx.x; idx < HID * WSTRIDE; idx += blockDim.x) {
        int n = idx / WSTRIDE, k = idx - n * WSTRIDE;
        if (k < HID) {
            float w = W[k * HID + n];
            __nv_bfloat16 h = __float2bfloat16_rn(w);
            __nv_bfloat16 l = __float2bfloat16_rn(w - __bfloat162float(h));
            dh[idx] = h; dl[idx] = l;
        } else {
            dh[idx] = __float2bfloat16_rn(0.f);
            dl[idx] = __float2bfloat16_rn(0.f);
        }
    }
}

// ---------------------------------------------------------------------------
// Main kernel: 128 points x 1 part per CTA, mma.sync bf16 3-pass hidden layers
// ---------------------------------------------------------------------------
__global__ __launch_bounds__(TPB, 1) void main_kernel(
    const float* __restrict__ pts, const float* __restrict__ Btr, const float* __restrict__ Brot,
    const float* __restrict__ W0, const float* __restrict__ b0,
    const float* __restrict__ b1, const float* __restrict__ b2,
    const float* __restrict__ W3, const float* __restrict__ b3)
{
    extern __shared__ char sm[];
    __nv_bfloat16* actHi = (__nv_bfloat16*)(sm + OFF_ACT_HI);
    __nv_bfloat16* actLo = (__nv_bfloat16*)(sm + OFF_ACT_LO);
    __nv_bfloat16* wHi   = (__nv_bfloat16*)(sm + OFF_W_HI);
    __nv_bfloat16* wLo   = (__nv_bfloat16*)(sm + OFF_W_LO);
    float* w0s = (float*)(sm + OFF_F32);
    float* b0s = w0s + 896;
    float* b1s = b0s + 128;
    float* b2s = b1s + 128;
    float* w3s = b2s + 128;

    int tid = threadIdx.x;
    int j = blockIdx.y;
    int v0 = blockIdx.x * MTILE;
    int w = tid >> 5, lane = tid & 31;
    int g = lane >> 2, tig = lane & 3;

    // ---- stage layer-1 weights + w0 + biases ----
    {
        const uint4* s1 = (const uint4*)&g_Wt[0][0][j][0];
        const uint4* s2 = (const uint4*)&g_Wt[0][1][j][0];
        uint4* d1 = (uint4*)wHi;
        uint4* d2 = (uint4*)wLo;
        for (int i = tid; i < (HID * WSTRIDE) / 8; i += TPB) { d1[i] = s1[i]; d2[i] = s2[i]; }
        for (int i = tid; i < 896; i += TPB) w0s[i] = W0[j * 896 + i];
        if (tid < 128) {
            b0s[tid] = b0[j * 128 + tid];
            b1s[tid] = b1[j * 128 + tid];
            b2s[tid] = b2[j * 128 + tid];
            w3s[tid] = W3[j * 128 + tid];
        }
    }

    // ---- geometry (both halves of the block compute the same row redundantly) ----
    int m = tid & (MTILE - 1);
    int half = tid >> 7;
    int v = v0 + m;
    int vc = v < NV ? v : NV - 1;
    float xk[7];
    {
        float px = pts[vc * 3 + 0] - Btr[j * 3 + 0];
        float py = pts[vc * 3 + 1] - Btr[j * 3 + 1];
        float pz = pts[vc * 3 + 2] - Btr[j * 3 + 2];
        const float* R = Brot + j * 9;
        float plx = R[0] * px + R[3] * py + R[6] * pz;
        float ply = R[1] * px + R[4] * py + R[7] * pz;
        float plz = R[2] * px + R[5] * py + R[8] * pz;
        float ox = 0.f, oy = 0.f, oz = 0.f;
        #pragma unroll
        for (int gi = 0; gi < NG; gi++) {
            const float* gg = g_geom[j][gi];
            float dx = plx - gg[0], dy = ply - gg[1], dz = plz - gg[2];
            float arg = dx * gg[3] + dy * gg[4] + dz * gg[5] + gg[6];
            float ww = 1.0f / (1.0f + expf(-arg));
            float ax = -gg[7] * ww, ay = -gg[8] * ww, az = -gg[9] * ww;
            float ang = sqrtf(ax * ax + ay * ay + az * az);
            float inv = (ang < 1e-12f) ? 1.0f : (1.0f / ang);
            float ux = ax * inv, uy = ay * inv, uz = az * inv;
            float cc = cosf(ang), ss = sinf(ang);
            float C = 1.0f - cc;
            float qx = plx - gg[10], qy = ply - gg[11], qz = plz - gg[12];
            float rx = (cc + ux * ux * C) * qx + (ux * uy * C - uz * ss) * qy + (ux * uz * C + uy * ss) * qz;
            float ry = (uy * ux * C + uz * ss) * qx + (cc + uy * uy * C) * qy + (uy * uz * C - ux * ss) * qz;
            float rz = (uz * ux * C - uy * ss) * qx + (uz * uy * C + ux * ss) * qy + (cc + uz * uz * C) * qz;
            ox += rx + gg[10] - plx;
            oy += ry + gg[11] - ply;
            oz += rz + gg[12] - plz;
        }
        xk[0] = plx + ox; xk[1] = ply + oy; xk[2] = plz + oz;
        xk[3] = g_c[j][0]; xk[4] = g_c[j][1]; xk[5] = g_c[j][2]; xk[6] = g_c[j][3];
    }
    __syncthreads();   // weights + biases staged

    // ---- layer0 (7 -> 128): each half computes 64 outputs of its row ----
    {
        int nbeg = half * 64;
        #pragma unroll
        for (int n = 0; n < 64; n += 2) {
            int nn = nbeg + n;
            float s0 = b0s[nn], s1 = b0s[nn + 1];
            #pragma unroll
            for (int k = 0; k < 7; k++) {
                s0 += xk[k] * w0s[k * 128 + nn];
                s1 += xk[k] * w0s[k * 128 + nn + 1];
            }
            uint32_t lo;
            uint32_t hi = packsplit_hi(sp100f(s0), sp100f(s1), lo);
            *(uint32_t*)(actHi + m * WSTRIDE + nn) = hi;
            *(uint32_t*)(actLo + m * WSTRIDE + nn) = lo;
        }
    }
    __syncthreads();

    int m0 = w * 16 + g;   // mma row base for this thread
    float acc[16][4];

    // ================= layer 1 =================
    #pragma unroll
    for (int nt = 0; nt < 16; nt++)
        #pragma unroll
        for (int q = 0; q < 4; q++) acc[nt][q] = 0.f;

    #pragma unroll
    for (int kk = 0; kk < 8; kk++) {
        int c = kk * 16 + tig * 2;
        uint32_t ah[4], al[4];
        ah[0] = lds32(actHi + m0 * WSTRIDE + c);
        ah[1] = lds32(actHi + (m0 + 8) * WSTRIDE + c);
        ah[2] = lds32(actHi + m0 * WSTRIDE + c + 8);
        ah[3] = lds32(actHi + (m0 + 8) * WSTRIDE + c + 8);
        al[0] = lds32(actLo + m0 * WSTRIDE + c);
        al[1] = lds32(actLo + (m0 + 8) * WSTRIDE + c);
        al[2] = lds32(actLo + m0 * WSTRIDE + c + 8);
        al[3] = lds32(actLo + (m0 + 8) * WSTRIDE + c + 8);
        #pragma unroll
        for (int nt = 0; nt < 16; nt++) {
            int nr = nt * 8 + g;
            uint32_t bh[2], bl[2];
            bh[0] = lds32(wHi + nr * WSTRIDE + c);
            bh[1] = lds32(wHi + nr * WSTRIDE + c + 8);
            bl[0] = lds32(wLo + nr * WSTRIDE + c);
            bl[1] = lds32(wLo + nr * WSTRIDE + c + 8);
            mma16816(acc[nt], ah, bh);
            mma16816(acc[nt], al, bh);
            mma16816(acc[nt], ah, bl);
        }
    }
    __syncthreads();   // all warps done reading act + weights

    // ---- epilogue layer1: bias + softplus + split back to act; restage W2 ----
    #pragma unroll
    for (int nt = 0; nt < 16; nt++) {
        int n = nt * 8 + tig * 2;
        uint32_t lo, hi;
        hi = packsplit_hi(sp100f(acc[nt][0] + b1s[n]), sp100f(acc[nt][1] + b1s[n + 1]), lo);
        *(uint32_t*)(actHi + m0 * WSTRIDE + n) = hi;
        *(uint32_t*)(actLo + m0 * WSTRIDE + n) = lo;
        hi = packsplit_hi(sp100f(acc[nt][2] + b2s[0] * 0.f + b1s[n]), sp100f(acc[nt][3] + b1s[n + 1]), lo);
        *(uint32_t*)(actHi + (m0 + 8) * WSTRIDE + n) = hi;
        *(uint32_t*)(actLo + (m0 + 8) * WSTRIDE + n) = lo;
    }
    {
        const uint4* s1 = (const uint4*)&g_Wt[1][0][j][0];
        const uint4* s2 = (const uint4*)&g_Wt[1][1][j][0];
        uint4* d1 = (uint4*)wHi;
        uint4* d2 = (uint4*)wLo;
        for (int i = tid; i < (HID * WSTRIDE) / 8; i += TPB) { d1[i] = s1[i]; d2[i] = s2[i]; }
    }
    __syncthreads();

    // ================= layer 2 =================
    #pragma unroll
    for (int nt = 0; nt < 16; nt++)
        #pragma unroll
        for (int q = 0; q < 4; q++) acc[nt][q] = 0.f;

    #pragma unroll
    for (int kk = 0; kk < 8; kk++) {
        int c = kk * 16 + tig * 2;
        uint32_t ah[4], al[4];
        ah[0] = lds32(actHi + m0 * WSTRIDE + c);
        ah[1] = lds32(actHi + (m0 + 8) * WSTRIDE + c);
        ah[2] = lds32(actHi + m0 * WSTRIDE + c + 8);
        ah[3] = lds32(actHi + (m0 + 8) * WSTRIDE + c + 8);
        al[0] = lds32(actLo + m0 * WSTRIDE + c);
        al[1] = lds32(actLo + (m0 + 8) * WSTRIDE + c);
        al[2] = lds32(actLo + m0 * WSTRIDE + c + 8);
        al[3] = lds32(actLo + (m0 + 8) * WSTRIDE + c + 8);
        #pragma unroll
        for (int nt = 0; nt < 16; nt++) {
            int nr = nt * 8 + g;
            uint32_t bh[2], bl[2];
            bh[0] = lds32(wHi + nr * WSTRIDE + c);
            bh[1] = lds32(wHi + nr * WSTRIDE + c + 8);
            bl[0] = lds32(wLo + nr * WSTRIDE + c);
            bl[1] = lds32(wLo + nr * WSTRIDE + c + 8);
            mma16816(acc[nt], ah, bh);
            mma16816(acc[nt], al, bh);
            mma16816(acc[nt], ah, bl);
        }
    }

    // ---- epilogue layer2 + layer3 dot + quad reduce ----
    {
        float dot0 = 0.f, dot1 = 0.f;
        #pragma unroll
        for (int nt = 0; nt < 16; nt++) {
            int n = nt * 8 + tig * 2;
            dot0 += sp100f(acc[nt][0] + b2s[n]) * w3s[n];
            dot0 += sp100f(acc[nt][1] + b2s[n + 1]) * w3s[n + 1];
            dot1 += sp100f(acc[nt][2] + b2s[n]) * w3s[n];
            dot1 += sp100f(acc[nt][3] + b2s[n + 1]) * w3s[n + 1];
        }
        dot0 += __shfl_xor_sync(0xffffffffu, dot0, 1);
        dot0 += __shfl_xor_sync(0xffffffffu, dot0, 2);
        dot1 += __shfl_xor_sync(0xffffffffu, dot1, 1);
        dot1 += __shfl_xor_sync(0xffffffffu, dot1, 2);
        if (tig == 0) {
            float bb = b3[j];
            int va = v0 + m0;
            int vb = v0 + m0 + 8;
            if (va < NV) g_pred[j][va] = dot0 + bb;
            if (vb < NV) g_pred[j][vb] = dot1 + bb;
        }
    }
}

// ---------------------------------------------------------------------------
// Softmin blend over parts
// ---------------------------------------------------------------------------
__global__ void softmin_kernel(float* __restrict__ out) {
    int v = blockIdx.x * blockDim.x + threadIdx.x;
    if (v >= NV) return;
    float p[NJ];
    float mn = 3.0e38f;
    #pragma unroll
    for (int j = 0; j < NJ; j++) { p[j] = g_pred[j][v]; mn = fminf(mn, p[j]); }
    float se = 0.f, sd = 0.f;
    #pragma unroll
    for (int j = 0; j < NJ; j++) {
        float d = p[j] - mn;
        float e = expf(-200.0f * d);
        se += e;
        sd += d * e;
    }
    out[v] = sd / se + mn;
}

extern "C" void kernel_launch(void* const* d_in, const int* in_sizes, int n_in,
                              void* d_out, int out_size)
{
    const float* pts    = (const float*)d_in[0];
    const float* Bcond  = (const float*)d_in[1];
    const float* Btr    = (const float*)d_in[2];
    const float* Brot   = (const float*)d_in[3];
    const float* Bneigh = (const float*)d_in[4];
    const float* alpha  = (const float*)d_in[5];
    const float* beta   = (const float*)d_in[6];
    const float* cW0 = (const float*)d_in[7];
    const float* cb0 = (const float*)d_in[8];
    const float* cW1 = (const float*)d_in[9];
    const float* cb1 = (const float*)d_in[10];
    const float* cW2 = (const float*)d_in[11];
    const float* cb2 = (const float*)d_in[12];
    const float* W0  = (const float*)d_in[13];
    const float* b0  = (const float*)d_in[14];
    const float* W1  = (const float*)d_in[15];
    const float* b1  = (const float*)d_in[16];
    const float* W2  = (const float*)d_in[17];
    const float* b2  = (const float*)d_in[18];
    const float* W3  = (const float*)d_in[19];
    const float* b3  = (const float*)d_in[20];

    cudaFuncSetAttribute(main_kernel, cudaFuncAttributeMaxDynamicSharedMemorySize, SMEM_BYTES);

    pre_kernel<<<NJ, 32>>>(Bcond, Bneigh, alpha, beta, cW0, cb0, cW1, cb1, cW2, cb2);
    wconv_kernel<<<dim3(NJ, 2), 256>>>(W1, W2);

    dim3 grid((NV + MTILE - 1) / MTILE, NJ);
    main_kernel<<<grid, TPB, SMEM_BYTES>>>(pts, Btr, Brot, W0, b0, b1, b2, W3, b3);

    softmin_kernel<<<(NV + 255) / 256, 256>>>((float*)d_out);
}